// round 17
// baseline (speedup 1.0000x reference)
#include <cuda_runtime.h>
#include <cuda_fp16.h>
#include <cstdint>

#define NA 100000
#define NB 100000
#define IN_DIM 256
#define OUT_DIM 256
#define NE 320000
#define LN_EPS 1e-5f

#define NBIN (2 * NA)
#define SCAN_B 512
#define NBLK ((NBIN + SCAN_B - 1) / SCAN_B)   // 391

#define CONV_BLOCKS ((int)(((size_t)NB * 256 / 8 + 255) / 256))   // 12500
#define HIST_BLOCKS ((2 * NE + 255) / 256)                        // 2500

// ---------------- scratch (device globals; no allocation allowed) -----------
__device__ __half g_xh[(size_t)NB * 256];            // x_B quantized to fp16
__device__ __half g_aggh[(size_t)2 * NA * 256];      // per-path mean+bias (fp16)
__device__ float g_cnt[NBIN];                        // 1.0 if deg>0 else 0.0
__device__ __half g_Sh[(size_t)NBIN * 256];          // per-bin MEAN, fp16
__device__ __half g_Wt[512 * 256];                   // Wcat^T [n][k], fp16
__device__ int g_hist[NBIN];
__device__ int g_rowptr[NBIN];
__device__ int g_cursor[NBIN];
__device__ int g_elist[2 * NE];
__device__ int g_blocksums[SCAN_B];

// ---------------- helpers ----------------------------------------------------
__device__ __forceinline__ uint32_t smem_u32(const void* p) {
    uint32_t a;
    asm("{ .reg .u64 t; cvta.to.shared.u64 t, %1; cvt.u32.u64 %0, t; }" : "=r"(a) : "l"(p));
    return a;
}
__device__ __forceinline__ void ldsm_x4(uint32_t& r0, uint32_t& r1, uint32_t& r2,
                                        uint32_t& r3, uint32_t addr) {
    asm volatile("ldmatrix.sync.aligned.m8n8.x4.shared.b16 {%0,%1,%2,%3}, [%4];"
                 : "=r"(r0), "=r"(r1), "=r"(r2), "=r"(r3) : "r"(addr));
}
__device__ __forceinline__ void mma_fp16(float* c, const uint32_t* a, const uint32_t* b) {
    asm volatile("mma.sync.aligned.m16n8k16.row.col.f32.f16.f16.f32 "
                 "{%0,%1,%2,%3}, {%4,%5,%6,%7}, {%8,%9}, {%0,%1,%2,%3};"
                 : "+f"(c[0]), "+f"(c[1]), "+f"(c[2]), "+f"(c[3])
                 : "r"(a[0]), "r"(a[1]), "r"(a[2]), "r"(a[3]), "r"(b[0]), "r"(b[1]));
}
#define CP_ASYNC16(sm, gp) \
    asm volatile("cp.async.cg.shared.global [%0], [%1], 16;" \
                 :: "r"(sm), "l"(gp) : "memory")
#define CP_ASYNC16Z(sm, gp, sz) \
    asm volatile("cp.async.cg.shared.global [%0], [%1], 16, %2;" \
                 :: "r"(sm), "l"(gp), "r"(sz) : "memory")
#define CP_COMMIT() asm volatile("cp.async.commit_group;" ::: "memory")
#define CP_WAIT0()  asm volatile("cp.async.wait_group 0;" ::: "memory")
#define CP_WAIT1()  asm volatile("cp.async.wait_group 1;" ::: "memory")

// ---------------- W transpose prep + hist zero (merged) ----------------------
__global__ __launch_bounds__(256) void splitW_kernel(const float* __restrict__ W0,
                                                     const float* __restrict__ W1) {
    int n = blockIdx.x;
    int k = threadIdx.x;
    float w = (n < 256) ? W0[k * 256 + n] : W1[k * 256 + (n - 256)];
    g_Wt[n * 256 + k] = __float2half_rn(w);

    int zi = blockIdx.x * 256 + threadIdx.x;
    if (zi < NBIN / 4)
        reinterpret_cast<int4*>(g_hist)[zi] = make_int4(0, 0, 0, 0);
}

// ---------------- x convert + histogram (merged grid) ------------------------
__global__ __launch_bounds__(256) void convhist_kernel(
    const float* __restrict__ xB,
    const int* __restrict__ ei0, const int* __restrict__ ei1)
{
    if (blockIdx.x < CONV_BLOCKS) {
        size_t i = (size_t)blockIdx.x * 256 + threadIdx.x;   // one uint4 (8 halves)
        const size_t n8 = (size_t)NB * 256 / 8;
        if (i >= n8) return;
        const float4* src = reinterpret_cast<const float4*>(xB) + i * 2;
        float4 v0 = src[0], v1 = src[1];
        __half2 h0 = __floats2half2_rn(v0.x, v0.y);
        __half2 h1 = __floats2half2_rn(v0.z, v0.w);
        __half2 h2 = __floats2half2_rn(v1.x, v1.y);
        __half2 h3 = __floats2half2_rn(v1.z, v1.w);
        uint4 o;
        o.x = *reinterpret_cast<uint32_t*>(&h0);
        o.y = *reinterpret_cast<uint32_t*>(&h1);
        o.z = *reinterpret_cast<uint32_t*>(&h2);
        o.w = *reinterpret_cast<uint32_t*>(&h3);
        reinterpret_cast<uint4*>(g_xh)[i] = o;
        return;
    }
    int i = (blockIdx.x - CONV_BLOCKS) * 256 + threadIdx.x;
    if (i >= 2 * NE) return;
    int p = (i >= NE) ? 1 : 0;
    int e = i - p * NE;
    const int* __restrict__ ei = p ? ei1 : ei0;
    int dst = ei[e + NE];
    atomicAdd(&g_hist[p * NA + dst], 1);
}

// ---------------- CSR scan ----------------------------------------------------
__global__ __launch_bounds__(SCAN_B) void scanA_kernel() {
    __shared__ int sh[SCAN_B];
    int i = blockIdx.x * SCAN_B + threadIdx.x;
    sh[threadIdx.x] = (i < NBIN) ? g_hist[i] : 0;
    __syncthreads();
    for (int d = SCAN_B / 2; d > 0; d >>= 1) {
        if (threadIdx.x < d) sh[threadIdx.x] += sh[threadIdx.x + d];
        __syncthreads();
    }
    if (threadIdx.x == 0) g_blocksums[blockIdx.x] = sh[0];
}

// scanC with merged scanB: each block reduces blocksums[0..bid) itself.
__global__ __launch_bounds__(SCAN_B) void scanC_kernel() {
    __shared__ int sh[SCAN_B];
    __shared__ int sred[SCAN_B];
    int tid = threadIdx.x;
    int bid = blockIdx.x;

    int v0 = (tid < bid && tid < NBLK) ? g_blocksums[tid] : 0;
    sred[tid] = v0;
    __syncthreads();
    for (int d = SCAN_B / 2; d > 0; d >>= 1) {
        if (tid < d) sred[tid] += sred[tid + d];
        __syncthreads();
    }
    int blockoff = sred[0];

    int i = bid * SCAN_B + tid;
    int v = (i < NBIN) ? g_hist[i] : 0;
    sh[tid] = v;
    __syncthreads();
    for (int d = 1; d < SCAN_B; d <<= 1) {
        int t = (tid >= d) ? sh[tid - d] : 0;
        __syncthreads();
        sh[tid] += t;
        __syncthreads();
    }
    if (i < NBIN) {
        int excl = sh[tid] - v + blockoff;
        g_rowptr[i] = excl;
        g_cursor[i] = excl;
        g_cnt[i] = (v > 0) ? 1.0f : 0.0f;
    }
}

__global__ __launch_bounds__(256) void fill_kernel(
    const int* __restrict__ ei0, const int* __restrict__ ei1)
{
    int i = blockIdx.x * 256 + threadIdx.x;
    if (i >= 2 * NE) return;
    int p = (i >= NE) ? 1 : 0;
    int e = i - p * NE;
    const int* __restrict__ ei = p ? ei1 : ei0;
    int src = ei[e];
    int dst = ei[e + NE];
    int pos = atomicAdd(&g_cursor[p * NA + dst], 1);
    g_elist[pos] = src;
}

// ---------------- aggregate: warp per bin; masked 4-wide fp16 gather ---------
__global__ __launch_bounds__(256) void agg_kernel() {
    int w = (blockIdx.x * 256 + threadIdx.x) >> 5;
    int lane = threadIdx.x & 31;
    if (w >= NBIN) return;
    int start = g_rowptr[w];
    int deg = g_hist[w];

    float a[8] = {0.f, 0.f, 0.f, 0.f, 0.f, 0.f, 0.f, 0.f};

    for (int j = 0; j < deg; j += 4) {
        int m = deg - j;
        // indices: clamp out-of-range to idx0 (duplicate load, masked out below)
        int s0 = __ldg(&g_elist[start + j]);
        int s1 = __ldg(&g_elist[start + j + ((m > 1) ? 1 : 0)]);
        int s2 = __ldg(&g_elist[start + j + ((m > 2) ? 2 : 0)]);
        int s3 = __ldg(&g_elist[start + j + ((m > 3) ? 3 : 0)]);
        float m1 = (m > 1) ? 1.f : 0.f;
        float m2 = (m > 2) ? 1.f : 0.f;
        float m3 = (m > 3) ? 1.f : 0.f;
        uint4 v0 = *(reinterpret_cast<const uint4*>(g_xh + (size_t)s0 * 256) + lane);
        uint4 v1 = *(reinterpret_cast<const uint4*>(g_xh + (size_t)s1 * 256) + lane);
        uint4 v2 = *(reinterpret_cast<const uint4*>(g_xh + (size_t)s2 * 256) + lane);
        uint4 v3 = *(reinterpret_cast<const uint4*>(g_xh + (size_t)s3 * 256) + lane);
        const uint32_t* pv0 = reinterpret_cast<const uint32_t*>(&v0);
        const uint32_t* pv1 = reinterpret_cast<const uint32_t*>(&v1);
        const uint32_t* pv2 = reinterpret_cast<const uint32_t*>(&v2);
        const uint32_t* pv3 = reinterpret_cast<const uint32_t*>(&v3);
#pragma unroll
        for (int q = 0; q < 4; q++) {
            float2 f0 = __half22float2(*reinterpret_cast<const __half2*>(&pv0[q]));
            float2 f1 = __half22float2(*reinterpret_cast<const __half2*>(&pv1[q]));
            float2 f2 = __half22float2(*reinterpret_cast<const __half2*>(&pv2[q]));
            float2 f3 = __half22float2(*reinterpret_cast<const __half2*>(&pv3[q]));
            a[q * 2]     += f0.x + m1 * f1.x + m2 * f2.x + m3 * f3.x;
            a[q * 2 + 1] += f0.y + m1 * f1.y + m2 * f2.y + m3 * f3.y;
        }
    }

    float inv = (deg > 0) ? 1.0f / (float)deg : 0.0f;
    __half2 h0 = __floats2half2_rn(a[0] * inv, a[1] * inv);
    __half2 h1 = __floats2half2_rn(a[2] * inv, a[3] * inv);
    __half2 h2 = __floats2half2_rn(a[4] * inv, a[5] * inv);
    __half2 h3 = __floats2half2_rn(a[6] * inv, a[7] * inv);
    uint4 hv;
    hv.x = *reinterpret_cast<uint32_t*>(&h0);
    hv.y = *reinterpret_cast<uint32_t*>(&h1);
    hv.z = *reinterpret_cast<uint32_t*>(&h2);
    hv.w = *reinterpret_cast<uint32_t*>(&h3);
    *reinterpret_cast<uint4*>(g_Sh + (size_t)w * 256 + lane * 8) = hv;
}

// ---------------- HMMA GEMM: agg = mean @ W + b (single-pass fp16) -----------
// grid (4, 782): bx = p*2+h, by = m-tile. K-chunk 64.
// Stage = [A 16KB | B 16KB] = 32KB; 2 stages = 64KB.
#define GBUF 32768
#define GSM_TOTAL (2 * GBUF)

__device__ __forceinline__ void gemm_issue(
    uint32_t sb, int tid, int m0,
    const __half* __restrict__ Ah, const __half* __restrict__ Bw,
    int kc)
{
#pragma unroll
    for (int l = 0; l < 4; l++) {
        int idx = l * 256 + tid;
        int r = idx >> 3, u = idx & 7;
        int grow = m0 + r;
        int ok = (grow < NA) ? 16 : 0;
        int grc = (grow < NA) ? grow : (NA - 1);
        uint32_t dst = sb + (uint32_t)(r * 128 + ((u ^ (r & 7)) << 4));
        const __half* src = Ah + (size_t)grc * 256 + kc * 64 + u * 8;
        CP_ASYNC16Z(dst, src, ok);
    }
#pragma unroll
    for (int l = 0; l < 4; l++) {
        int idx = l * 256 + tid;
        int n = idx >> 3, u = idx & 7;
        uint32_t dst = sb + 16384u + (uint32_t)(n * 128 + ((u ^ (n & 7)) << 4));
        const __half* src = Bw + (size_t)n * 256 + kc * 64 + u * 8;
        CP_ASYNC16(dst, src);
    }
    CP_COMMIT();
}

__global__ __launch_bounds__(256, 2) void gemm_mma_kernel(
    const float* __restrict__ b0, const float* __restrict__ b1)
{
    extern __shared__ char smem[];
    const uint32_t sbase = smem_u32(smem);
    const int tid = threadIdx.x, lane = tid & 31, wid = tid >> 5;
    const int wm = wid & 3;
    const int wn = wid >> 2;
    const int p = blockIdx.x >> 1, h = blockIdx.x & 1;
    const int m0 = blockIdx.y * 128;

    const __half* __restrict__ Ah = g_Sh + (size_t)p * NA * 256;
    const __half* __restrict__ Bw = g_Wt + (size_t)(p * 256 + h * 128) * 256;

    float c[2][8][4];
#pragma unroll
    for (int mt = 0; mt < 2; mt++)
#pragma unroll
        for (int n8 = 0; n8 < 8; n8++)
#pragma unroll
            for (int q = 0; q < 4; q++) c[mt][n8][q] = 0.f;

    const int am = lane & 15;
    const int aoff = lane >> 4;
    const int asw = am & 7;
    const int bn = (lane & 7) | ((lane & 16) >> 1);
    const int boff = (lane >> 3) & 1;
    const int bsw = bn & 7;

    gemm_issue(sbase, tid, m0, Ah, Bw, 0);

    for (int kc = 0; kc < 4; kc++) {
        if (kc < 3) {
            gemm_issue(sbase + ((kc + 1) & 1) * GBUF, tid, m0, Ah, Bw, kc + 1);
            CP_WAIT1();
        } else {
            CP_WAIT0();
        }
        __syncthreads();
        const uint32_t sb = sbase + (kc & 1) * GBUF;

#pragma unroll
        for (int s = 0; s < 4; s++) {
            const int unit = (s << 1) | aoff;
            uint32_t ah[2][4];
#pragma unroll
            for (int mt = 0; mt < 2; mt++) {
                int arow = wm * 32 + mt * 16 + am;
                ldsm_x4(ah[mt][0], ah[mt][1], ah[mt][2], ah[mt][3],
                        sb + (uint32_t)(arow * 128) + ((unit ^ asw) << 4));
            }
            const int vhi = (s << 1) | boff;
#pragma unroll
            for (int g = 0; g < 4; g++) {
                int brow = wn * 64 + g * 16 + bn;
                uint32_t rb = sb + 16384u + (uint32_t)(brow * 128);
                uint32_t bh[4];
                ldsm_x4(bh[0], bh[1], bh[2], bh[3], rb + ((vhi ^ bsw) << 4));
#pragma unroll
                for (int mt = 0; mt < 2; mt++) {
                    mma_fp16(c[mt][2 * g],     ah[mt], &bh[0]);
                    mma_fp16(c[mt][2 * g + 1], ah[mt], &bh[2]);
                }
            }
        }
        __syncthreads();
    }

    // ---- epilogue: + bias flag -> g_aggh (fp16) -----------------------------
    const float* __restrict__ bias = p ? b1 : b0;
    __half* __restrict__ dst = g_aggh + (size_t)p * NA * 256;
#pragma unroll
    for (int mt = 0; mt < 2; mt++) {
#pragma unroll
        for (int rr = 0; rr < 2; rr++) {
            int row = m0 + wm * 32 + mt * 16 + rr * 8 + (lane >> 2);
            if (row >= NA) continue;
            float bf = g_cnt[p * NA + row];
            __half* orow = dst + (size_t)row * 256;
#pragma unroll
            for (int n8 = 0; n8 < 8; n8++) {
                int col = h * 128 + wn * 64 + n8 * 8 + (lane & 3) * 2;
                __half2 o = __floats2half2_rn(
                    c[mt][n8][rr * 2 + 0] + bias[col] * bf,
                    c[mt][n8][rr * 2 + 1] + bias[col + 1] * bf);
                *reinterpret_cast<__half2*>(orow + col) = o;
            }
        }
    }
}

// ---------------- finalize + outB zeroing (zero blocks FIRST) ----------------
#define FIN_BLOCKS ((NA * 32 + 255) / 256)                    // 12500
#define ZB_BLOCKS  ((int)(((size_t)NB * OUT_DIM / 4 + 255) / 256))  // 25000

__global__ __launch_bounds__(256) void finalize_kernel(
    const float* __restrict__ sem, const float* __restrict__ gamma,
    const float* __restrict__ beta, float* __restrict__ outA,
    float* __restrict__ outB)
{
    if (blockIdx.x < ZB_BLOCKS) {
        size_t i = (size_t)blockIdx.x * 256 + threadIdx.x;
        if (i < (size_t)NB * OUT_DIM / 4)
            reinterpret_cast<float4*>(outB)[i] = make_float4(0.f, 0.f, 0.f, 0.f);
        return;
    }
    int n = ((blockIdx.x - ZB_BLOCKS) * 256 + threadIdx.x) >> 5;
    int lane = threadIdx.x & 31;
    if (n >= NA) return;
    int base = lane * 8;

    const __half* a0p = g_aggh + (size_t)n * 256;
    const __half* a1p = g_aggh + ((size_t)NA + n) * 256;

    float a0[8], a1[8], sv[8];
    {
        uint4 v0 = *reinterpret_cast<const uint4*>(a0p + base);
        uint4 v1 = *reinterpret_cast<const uint4*>(a1p + base);
        const __half2* p0 = reinterpret_cast<const __half2*>(&v0);
        const __half2* p1 = reinterpret_cast<const __half2*>(&v1);
#pragma unroll
        for (int q = 0; q < 4; q++) {
            float2 f0 = __half22float2(p0[q]);
            float2 f1 = __half22float2(p1[q]);
            a0[q * 2] = f0.x; a0[q * 2 + 1] = f0.y;
            a1[q * 2] = f1.x; a1[q * 2 + 1] = f1.y;
        }
    }
    *reinterpret_cast<float4*>(&sv[0]) = *reinterpret_cast<const float4*>(sem + base);
    *reinterpret_cast<float4*>(&sv[4]) = *reinterpret_cast<const float4*>(sem + base + 4);

    float s0 = 0.f, s1 = 0.f;
#pragma unroll
    for (int i = 0; i < 8; i++) {
        s0 += tanhf(a0[i]) * sv[i];
        s1 += tanhf(a1[i]) * sv[i];
    }
#pragma unroll
    for (int o = 16; o > 0; o >>= 1) {
        s0 += __shfl_xor_sync(0xffffffffu, s0, o);
        s1 += __shfl_xor_sync(0xffffffffu, s1, o);
    }
    float m = fmaxf(s0, s1);
    float e0 = __expf(s0 - m), e1 = __expf(s1 - m);
    float w0 = e0 / (e0 + e1);
    float w1 = 1.0f - w0;

    float f[8];
    float sum = 0.f, sq = 0.f;
#pragma unroll
    for (int i = 0; i < 8; i++) {
        f[i] = fmaxf(w0 * a0[i] + w1 * a1[i], 0.f);
        sum += f[i];
        sq  += f[i] * f[i];
    }
#pragma unroll
    for (int o = 16; o > 0; o >>= 1) {
        sum += __shfl_xor_sync(0xffffffffu, sum, o);
        sq  += __shfl_xor_sync(0xffffffffu, sq, o);
    }
    float mu  = sum * (1.0f / 256.0f);
    float var = sq * (1.0f / 256.0f) - mu * mu;
    float rstd = rsqrtf(var + LN_EPS);

    float gm[8], bt[8];
    *reinterpret_cast<float4*>(&gm[0]) = *reinterpret_cast<const float4*>(gamma + base);
    *reinterpret_cast<float4*>(&gm[4]) = *reinterpret_cast<const float4*>(gamma + base + 4);
    *reinterpret_cast<float4*>(&bt[0]) = *reinterpret_cast<const float4*>(beta + base);
    *reinterpret_cast<float4*>(&bt[4]) = *reinterpret_cast<const float4*>(beta + base + 4);

    float o8[8];
#pragma unroll
    for (int i = 0; i < 8; i++)
        o8[i] = (f[i] - mu) * rstd * gm[i] + bt[i];

    float* op = outA + (size_t)n * 256 + base;
    *reinterpret_cast<float4*>(op)     = *reinterpret_cast<float4*>(&o8[0]);
    *reinterpret_cast<float4*>(op + 4) = *reinterpret_cast<float4*>(&o8[4]);
}

// ---------------- launch ----------------------------------------------------
extern "C" void kernel_launch(void* const* d_in, const int* in_sizes, int n_in,
                              void* d_out, int out_size)
{
    const float* x_B  = (const float*)d_in[1];
    const int*   ei0  = (const int*)d_in[2];
    const int*   ei1  = (const int*)d_in[3];
    const float* W0   = (const float*)d_in[4];
    const float* b0   = (const float*)d_in[5];
    const float* W1   = (const float*)d_in[6];
    const float* b1   = (const float*)d_in[7];
    const float* sem  = (const float*)d_in[8];
    const float* gam  = (const float*)d_in[9];
    const float* bet  = (const float*)d_in[10];

    float* outA = (float*)d_out;
    float* outB = outA + (size_t)NA * OUT_DIM;

    cudaFuncSetAttribute(gemm_mma_kernel,
                         cudaFuncAttributeMaxDynamicSharedMemorySize, GSM_TOTAL);

    splitW_kernel<<<512, 256>>>(W0, W1);                     // W prep + hist zero
    convhist_kernel<<<CONV_BLOCKS + HIST_BLOCKS, 256>>>(x_B, ei0, ei1);
    scanA_kernel<<<NBLK, SCAN_B>>>();
    scanC_kernel<<<NBLK, SCAN_B>>>();                        // merged scanB+scanC
    fill_kernel<<<(2 * NE + 255) / 256, 256>>>(ei0, ei1);

    agg_kernel<<<(NBIN * 32 + 255) / 256, 256>>>();

    {
        dim3 grid(4, (NA + 127) / 128);
        gemm_mma_kernel<<<grid, 256, GSM_TOTAL>>>(b0, b1);
    }

    finalize_kernel<<<FIN_BLOCKS + ZB_BLOCKS, 256>>>(sem, gam, bet, outA, outB);
}